// round 6
// baseline (speedup 1.0000x reference)
#include <cuda_runtime.h>
#include <cuda_bf16.h>
#include <cstdint>

// BasicMFNet: embed_user [8192,64] f32, embed_item [16384,64] f32,
// indices [2,200000] (int32 or int64 — detected at runtime), ratings [200000] f32.
// Output: pred [U*I] | label [U*I] | ratio (1)  -- all float32.
constexpr int U = 8192;
constexpr int I = 16384;
constexpr int H = 64;

constexpr int TILE = 128;        // M and N tile
constexpr int KC   = 32;         // k chunk (two chunks cover H=64)
constexpr int NCOLF = I / TILE;  // 128 column-tile flags
constexpr int NROWF = U / TILE;  // 64 row-tile flags

// Device scratch (no allocations allowed anywhere).
__device__ float g_eu[U * H];     // masked user embeddings
__device__ float g_ei[I * H];     // masked item embeddings
__device__ int   g_umask[U];
__device__ int   g_imask[I];
__device__ int   g_colflag[NCOLF];
__device__ int   g_rowflag[NROWF];
__device__ int   g_idx_is_i32;    // 1 if indices buffer is int32, 0 if int64

// ---------------------------------------------------------------------------
// Packed f32x2 helpers (Blackwell FFMA2 — PTX-only path, 2x fp32 FMA rate)
// ---------------------------------------------------------------------------
__device__ __forceinline__ unsigned long long dup_f32(float x) {
    unsigned long long r;
    unsigned xi = __float_as_uint(x);
    asm("mov.b64 %0, {%1, %1};" : "=l"(r) : "r"(xi));
    return r;
}
__device__ __forceinline__ void ffma2(unsigned long long& d,
                                      unsigned long long a,
                                      unsigned long long b) {
    asm("fma.rn.f32x2 %0, %1, %2, %0;" : "+l"(d) : "l"(a), "l"(b));
}

// Read index pair (u, v) honoring the detected dtype.
__device__ __forceinline__ void read_uv(const void* idx, int nnz, int t,
                                        int& u, int& v) {
    if (g_idx_is_i32) {
        const int* p = (const int*)idx;
        u = p[t];
        v = p[nnz + t];
    } else {
        const long long* p = (const long long*)idx;
        u = (int)p[t];
        v = (int)p[nnz + t];
    }
}

// ---------------------------------------------------------------------------
// Kernel 0: detect index dtype. For int64 values < 2^31, every odd int32 word
// is 0. For real int32 index data (values in [0, 8192)), 1024 odd words being
// all zero is probabilistically impossible. Deterministic for fixed input.
// ---------------------------------------------------------------------------
__global__ void k_detect_dtype(const int* __restrict__ idx_w32, int n_words) {
    int t = blockIdx.x * blockDim.x + threadIdx.x;   // samples odd words
    int w = 2 * t + 1;
    if (w < n_words && idx_w32[w] != 0) g_idx_is_i32 = 1;
}

// ---------------------------------------------------------------------------
// Kernel 1: zero masks + tile flags + dtype flag (tiny)
// ---------------------------------------------------------------------------
__global__ void k_zero_masks() {
    int t = blockIdx.x * blockDim.x + threadIdx.x;
    if (t < U) g_umask[t] = 0;
    if (t < I) g_imask[t] = 0;
    if (t < NCOLF) g_colflag[t] = 0;
    if (t < NROWF) g_rowflag[t] = 0;
    if (t == 0) g_idx_is_i32 = 0;
}

// ---------------------------------------------------------------------------
// Kernel 2: set masks + tile flags from indices (bounds-guarded)
// ---------------------------------------------------------------------------
__global__ void k_set_masks(const void* __restrict__ idx, int nnz) {
    int t = blockIdx.x * blockDim.x + threadIdx.x;
    if (t >= nnz) return;
    int u, v;
    read_uv(idx, nnz, t, u, v);
    if (u >= 0 && u < U) { g_umask[u] = 1; g_rowflag[u >> 7] = 1; }
    if (v >= 0 && v < I) { g_imask[v] = 1; g_colflag[v >> 7] = 1; }
}

// ---------------------------------------------------------------------------
// Kernel 3: build masked embedding copies + write ratio
// ---------------------------------------------------------------------------
__global__ void k_build_scratch(const float* __restrict__ eu,
                                const float* __restrict__ ei,
                                float* __restrict__ out, int nnz,
                                long long out_size) {
    int t = blockIdx.x * blockDim.x + threadIdx.x;
    const int NU4 = U * (H / 4);
    const int NI4 = I * (H / 4);
    if (t < NU4) {
        int row = t / (H / 4);
        float4 v = reinterpret_cast<const float4*>(eu)[t];
        if (!g_umask[row]) v = make_float4(0.f, 0.f, 0.f, 0.f);
        reinterpret_cast<float4*>(g_eu)[t] = v;
    } else if (t < NU4 + NI4) {
        int t2 = t - NU4;
        int row = t2 / (H / 4);
        float4 v = reinterpret_cast<const float4*>(ei)[t2];
        if (!g_imask[row]) v = make_float4(0.f, 0.f, 0.f, 0.f);
        reinterpret_cast<float4*>(g_ei)[t2] = v;
    }
    if (t == 0 && out_size > 2ll * U * I) {
        out[2ull * U * I] = (float)(((double)U * (double)I) / (double)nnz);
    }
}

// ---------------------------------------------------------------------------
// Kernel 4: GEMM  pred = g_eu * g_ei^T  (128x128 tile, 8x8 microtile split as
// (4+4)x(4+4) at stride 64 -> conflict-free LDS.128 on both operands).
// Epilogue also zero-fills the matching label tile (overlaps the 537 MB label
// zero-fill with GEMM compute instead of a serial pass).
// ---------------------------------------------------------------------------
__global__ void __launch_bounds__(256, 2) k_gemm(float* __restrict__ out) {
    const int bx = blockIdx.x;            // column tile (items)
    const int by = blockIdx.y;            // row tile (users)
    const int m0 = by * TILE;
    const int n0 = bx * TILE;
    const int tid = threadIdx.x;
    // Split microtile: rows {tm4a+i, tm4a+64+i}, cols {tn4a+j, tn4a+64+j}
    const int tm4a = (tid >> 4) * 4;      // 16 row-groups of 4
    const int tn4a = (tid & 15) * 4;      // 16 col-groups of 4 (consecutive 16B)

    float* pred  = out;
    float* label = out + (size_t)U * I;

    const bool active = (g_rowflag[by] != 0) && (g_colflag[bx] != 0);

    if (!active) {
        // Whole tile provably zero: store zeros for pred and label.
        const ulonglong2 z = make_ulonglong2(0ull, 0ull);
        #pragma unroll
        for (int i = 0; i < 8; i++) {
            int row = m0 + (i < 4 ? tm4a + i : 64 + tm4a + (i - 4));
            size_t off = (size_t)row * I + n0 + tn4a;
            *reinterpret_cast<ulonglong2*>(pred + off)       = z;
            *reinterpret_cast<ulonglong2*>(pred + off + 64)  = z;
            *reinterpret_cast<ulonglong2*>(label + off)      = z;
            *reinterpret_cast<ulonglong2*>(label + off + 64) = z;
        }
        return;
    }

    __shared__ float As[KC][TILE];   // k-major (transposed) tiles
    __shared__ float Bs[KC][TILE];

    unsigned long long acc[8][4];    // [row][col-pair]
    #pragma unroll
    for (int i = 0; i < 8; i++)
        #pragma unroll
        for (int j = 0; j < 4; j++) acc[i][j] = 0ull;

    for (int kc = 0; kc < H / KC; kc++) {
        __syncthreads();
        // Load+transpose: 128 rows x 32 k per tile; lanes stride rows ->
        // conflict-free STS (bank = r).
        #pragma unroll
        for (int it = 0; it < 4; it++) {
            int id = tid + it * 256;          // 0..1023
            int r = id & 127;
            int c = id >> 7;                  // 0..7 (k-group of 4)
            float4 va = *reinterpret_cast<const float4*>(
                &g_eu[(size_t)(m0 + r) * H + kc * KC + c * 4]);
            As[c * 4 + 0][r] = va.x;
            As[c * 4 + 1][r] = va.y;
            As[c * 4 + 2][r] = va.z;
            As[c * 4 + 3][r] = va.w;
            float4 vb = *reinterpret_cast<const float4*>(
                &g_ei[(size_t)(n0 + r) * H + kc * KC + c * 4]);
            Bs[c * 4 + 0][r] = vb.x;
            Bs[c * 4 + 1][r] = vb.y;
            Bs[c * 4 + 2][r] = vb.z;
            Bs[c * 4 + 3][r] = vb.w;
        }
        __syncthreads();

        #pragma unroll 8
        for (int k = 0; k < KC; k++) {
            // A: 16B broadcast loads (2 distinct addrs/warp -> free)
            float4 a0 = *reinterpret_cast<const float4*>(&As[k][tm4a]);
            float4 a1 = *reinterpret_cast<const float4*>(&As[k][tm4a + 64]);
            // B: lanes 0-15 read consecutive 16B chunks (bytes 0..255) ->
            // conflict-free; lanes 16-31 broadcast the same addrs.
            ulonglong2 b0 = *reinterpret_cast<const ulonglong2*>(&Bs[k][tn4a]);
            ulonglong2 b1 = *reinterpret_cast<const ulonglong2*>(&Bs[k][tn4a + 64]);
            unsigned long long bp0 = b0.x, bp1 = b0.y, bp2 = b1.x, bp3 = b1.y;
            float av[8] = {a0.x, a0.y, a0.z, a0.w, a1.x, a1.y, a1.z, a1.w};
            #pragma unroll
            for (int i = 0; i < 8; i++) {
                unsigned long long ad = dup_f32(av[i]);
                ffma2(acc[i][0], ad, bp0);
                ffma2(acc[i][1], ad, bp1);
                ffma2(acc[i][2], ad, bp2);
                ffma2(acc[i][3], ad, bp3);
            }
        }
    }

    // Epilogue: store pred tile + zero label tile. Lanes 0-15 of a warp cover
    // 256 consecutive bytes per row-chunk -> fully coalesced STG.128.
    const ulonglong2 z = make_ulonglong2(0ull, 0ull);
    #pragma unroll
    for (int i = 0; i < 8; i++) {
        int row = m0 + (i < 4 ? tm4a + i : 64 + tm4a + (i - 4));
        size_t off = (size_t)row * I + n0 + tn4a;
        *reinterpret_cast<ulonglong2*>(pred + off) =
            make_ulonglong2(acc[i][0], acc[i][1]);
        *reinterpret_cast<ulonglong2*>(pred + off + 64) =
            make_ulonglong2(acc[i][2], acc[i][3]);
        *reinterpret_cast<ulonglong2*>(label + off)      = z;
        *reinterpret_cast<ulonglong2*>(label + off + 64) = z;
    }
}

// ---------------------------------------------------------------------------
// Kernel 5: scatter-add ratings into label (bounds-guarded)
// ---------------------------------------------------------------------------
__global__ void k_scatter(const void* __restrict__ idx,
                          const float* __restrict__ ratings,
                          float* __restrict__ out, int nnz) {
    int t = blockIdx.x * blockDim.x + threadIdx.x;
    if (t >= nnz) return;
    int u, v;
    read_uv(idx, nnz, t, u, v);
    if (u < 0 || u >= U || v < 0 || v >= I) return;
    float* label = out + (size_t)U * I;
    atomicAdd(&label[(size_t)u * I + v], ratings[t]);
}

// ---------------------------------------------------------------------------
extern "C" void kernel_launch(void* const* d_in, const int* in_sizes, int n_in,
                              void* d_out, int out_size) {
    const float* eu = (const float*)d_in[0];
    const float* ei = (const float*)d_in[1];
    const void*  idx = d_in[2];
    const float* ratings = (const float*)d_in[3];
    float* out = (float*)d_out;
    const int nnz = in_sizes[3];            // ratings count
    // Number of int32 words if buffer is int32: equals element count reported;
    // sample at most the first 2048 words for dtype detection.
    const int n_words = in_sizes[2] < 2048 ? in_sizes[2] : 2048;

    // 0/1. zero masks/flags + detect index dtype
    k_zero_masks<<<(I + 255) / 256, 256>>>();
    k_detect_dtype<<<4, 256>>>((const int*)idx, n_words);
    // 2. set masks/flags from indices
    k_set_masks<<<(nnz + 255) / 256, 256>>>(idx, nnz);
    // 3. masked embedding copies + ratio
    {
        int total = U * (H / 4) + I * (H / 4);
        k_build_scratch<<<(total + 255) / 256, 256>>>(eu, ei, out, nnz,
                                                      (long long)out_size);
    }
    // 4. GEMM (writes pred + zeros label)
    {
        dim3 grid(I / TILE, U / TILE);
        k_gemm<<<grid, 256>>>(out);
    }
    // 5. scatter ratings into label
    k_scatter<<<(nnz + 255) / 256, 256>>>(idx, ratings, out, nnz);
}

// round 7
// speedup vs baseline: 1.1084x; 1.1084x over previous
#include <cuda_runtime.h>
#include <cuda_bf16.h>
#include <cstdint>

// BasicMFNet: embed_user [8192,64] f32, embed_item [16384,64] f32,
// indices [2,200000] (int32 or int64 — detected at runtime), ratings [200000] f32.
// Output: pred [U*I] | label [U*I] | ratio (1)  -- all float32.
constexpr int U = 8192;
constexpr int I = 16384;
constexpr int H = 64;

constexpr int TILE = 128;        // M and N tile
constexpr int NCOLF = I / TILE;  // 128 column-tile flags
constexpr int NROWF = U / TILE;  // 64 row-tile flags

// Device scratch (no allocations allowed anywhere).
__device__ float g_eu[U * H];     // masked user embeddings
__device__ float g_ei[I * H];     // masked item embeddings
__device__ int   g_umask[U];
__device__ int   g_imask[I];
__device__ int   g_colflag[NCOLF];
__device__ int   g_rowflag[NROWF];
__device__ int   g_idx_is_i32;    // 1 if indices buffer is int32, 0 if int64

// ---------------------------------------------------------------------------
// Packed f32x2 helpers (Blackwell FFMA2 — PTX-only path, 2x fp32 FMA rate)
// ---------------------------------------------------------------------------
__device__ __forceinline__ unsigned long long dup_f32(float x) {
    unsigned long long r;
    unsigned xi = __float_as_uint(x);
    asm("mov.b64 %0, {%1, %1};" : "=l"(r) : "r"(xi));
    return r;
}
__device__ __forceinline__ void ffma2(unsigned long long& d,
                                      unsigned long long a,
                                      unsigned long long b) {
    asm("fma.rn.f32x2 %0, %1, %2, %0;" : "+l"(d) : "l"(a), "l"(b));
}

// Read index pair (u, v) honoring the detected dtype.
__device__ __forceinline__ void read_uv(const void* idx, int nnz, int t,
                                        int& u, int& v) {
    if (g_idx_is_i32) {
        const int* p = (const int*)idx;
        u = p[t];
        v = p[nnz + t];
    } else {
        const long long* p = (const long long*)idx;
        u = (int)p[t];
        v = (int)p[nnz + t];
    }
}

// ---------------------------------------------------------------------------
// Kernel 1: init — zero masks/flags, and block 0 detects index dtype.
// For int64 values < 2^31 every odd int32 word is 0; for genuine int32 index
// data 2048 odd words all being zero is probabilistically impossible.
// Only block 0 writes g_idx_is_i32 (unconditionally) -> no race, no pre-zero.
// ---------------------------------------------------------------------------
__global__ void k_init(const int* __restrict__ idx_w32, int n_words) {
    int t = blockIdx.x * blockDim.x + threadIdx.x;
    if (t < U) g_umask[t] = 0;
    if (t < I) g_imask[t] = 0;
    if (t < NCOLF) g_colflag[t] = 0;
    if (t < NROWF) g_rowflag[t] = 0;
    if (blockIdx.x == 0) {
        __shared__ int s_found;
        if (threadIdx.x == 0) s_found = 0;
        __syncthreads();
        int found = 0;
        for (int w = 2 * (int)threadIdx.x + 1; w < n_words; w += 2 * (int)blockDim.x)
            if (idx_w32[w] != 0) found = 1;
        if (found) s_found = 1;
        __syncthreads();
        if (threadIdx.x == 0) g_idx_is_i32 = s_found;
    }
}

// ---------------------------------------------------------------------------
// Kernel 2: set masks + tile flags from indices (bounds-guarded)
// ---------------------------------------------------------------------------
__global__ void k_set_masks(const void* __restrict__ idx, int nnz) {
    int t = blockIdx.x * blockDim.x + threadIdx.x;
    if (t >= nnz) return;
    int u, v;
    read_uv(idx, nnz, t, u, v);
    if (u >= 0 && u < U) { g_umask[u] = 1; g_rowflag[u >> 7] = 1; }
    if (v >= 0 && v < I) { g_imask[v] = 1; g_colflag[v >> 7] = 1; }
}

// ---------------------------------------------------------------------------
// Kernel 3: build masked embedding copies + write ratio
// ---------------------------------------------------------------------------
__global__ void k_build_scratch(const float* __restrict__ eu,
                                const float* __restrict__ ei,
                                float* __restrict__ out, int nnz,
                                long long out_size) {
    int t = blockIdx.x * blockDim.x + threadIdx.x;
    const int NU4 = U * (H / 4);
    const int NI4 = I * (H / 4);
    if (t < NU4) {
        int row = t / (H / 4);
        float4 v = reinterpret_cast<const float4*>(eu)[t];
        if (!g_umask[row]) v = make_float4(0.f, 0.f, 0.f, 0.f);
        reinterpret_cast<float4*>(g_eu)[t] = v;
    } else if (t < NU4 + NI4) {
        int t2 = t - NU4;
        int row = t2 / (H / 4);
        float4 v = reinterpret_cast<const float4*>(ei)[t2];
        if (!g_imask[row]) v = make_float4(0.f, 0.f, 0.f, 0.f);
        reinterpret_cast<float4*>(g_ei)[t2] = v;
    }
    if (t == 0 && out_size > 2ll * U * I) {
        out[2ull * U * I] = (float)(((double)U * (double)I) / (double)nnz);
    }
}

// ---------------------------------------------------------------------------
// Kernel 4: GEMM  pred = g_eu * g_ei^T.
// 128x128 tile, whole H=64 k-depth resident in smem (one load phase, one
// __syncthreads, 64 straight k-steps). 8x8 microtile split as (4+4)x(4+4) at
// stride 64 -> conflict-free LDS.128 on both operands. Epilogue zero-fills
// the matching label tile (overlaps label zeroing with GEMM compute).
// ---------------------------------------------------------------------------
__global__ void __launch_bounds__(256, 2) k_gemm(float* __restrict__ out) {
    const int bx = blockIdx.x;            // column tile (items)
    const int by = blockIdx.y;            // row tile (users)
    const int m0 = by * TILE;
    const int n0 = bx * TILE;
    const int tid = threadIdx.x;
    const int tm4a = (tid >> 4) * 4;      // 16 row-groups of 4
    const int tn4a = (tid & 15) * 4;      // 16 col-groups of 4 (consecutive 16B)

    float* pred  = out;
    float* label = out + (size_t)U * I;

    const bool active = (g_rowflag[by] != 0) && (g_colflag[bx] != 0);

    if (!active) {
        // Whole tile provably zero: store zeros for pred and label.
        const ulonglong2 z = make_ulonglong2(0ull, 0ull);
        #pragma unroll
        for (int i = 0; i < 8; i++) {
            int row = m0 + (i < 4 ? tm4a + i : 64 + tm4a + (i - 4));
            size_t off = (size_t)row * I + n0 + tn4a;
            *reinterpret_cast<ulonglong2*>(pred + off)       = z;
            *reinterpret_cast<ulonglong2*>(pred + off + 64)  = z;
            *reinterpret_cast<ulonglong2*>(label + off)      = z;
            *reinterpret_cast<ulonglong2*>(label + off + 64) = z;
        }
        return;
    }

    __shared__ float As[H][TILE];   // k-major (transposed) tiles, 32 KB
    __shared__ float Bs[H][TILE];   // 32 KB

    // Single load phase: 128 rows x 64 k per tile. Warp lanes stride rows ->
    // conflict-free STS.32 (bank = r). 16 LDG.128 per thread, high MLP.
    #pragma unroll
    for (int it = 0; it < 8; it++) {
        int id = tid + it * 256;          // 0..2047
        int r = id & 127;
        int c = id >> 7;                  // 0..15 (k-group of 4)
        float4 va = *reinterpret_cast<const float4*>(
            &g_eu[(size_t)(m0 + r) * H + c * 4]);
        As[c * 4 + 0][r] = va.x;
        As[c * 4 + 1][r] = va.y;
        As[c * 4 + 2][r] = va.z;
        As[c * 4 + 3][r] = va.w;
        float4 vb = *reinterpret_cast<const float4*>(
            &g_ei[(size_t)(n0 + r) * H + c * 4]);
        Bs[c * 4 + 0][r] = vb.x;
        Bs[c * 4 + 1][r] = vb.y;
        Bs[c * 4 + 2][r] = vb.z;
        Bs[c * 4 + 3][r] = vb.w;
    }

    unsigned long long acc[8][4];    // [row][col-pair]
    #pragma unroll
    for (int i = 0; i < 8; i++)
        #pragma unroll
        for (int j = 0; j < 4; j++) acc[i][j] = 0ull;

    __syncthreads();

    #pragma unroll 8
    for (int k = 0; k < H; k++) {
        // A: 16B broadcast loads (2 distinct addrs/warp -> free)
        float4 a0 = *reinterpret_cast<const float4*>(&As[k][tm4a]);
        float4 a1 = *reinterpret_cast<const float4*>(&As[k][tm4a + 64]);
        // B: lanes 0-15 read consecutive 16B chunks (bytes 0..255) ->
        // conflict-free; lanes 16-31 broadcast the same addrs.
        ulonglong2 b0 = *reinterpret_cast<const ulonglong2*>(&Bs[k][tn4a]);
        ulonglong2 b1 = *reinterpret_cast<const ulonglong2*>(&Bs[k][tn4a + 64]);
        unsigned long long bp0 = b0.x, bp1 = b0.y, bp2 = b1.x, bp3 = b1.y;
        float av[8] = {a0.x, a0.y, a0.z, a0.w, a1.x, a1.y, a1.z, a1.w};
        #pragma unroll
        for (int i = 0; i < 8; i++) {
            unsigned long long ad = dup_f32(av[i]);
            ffma2(acc[i][0], ad, bp0);
            ffma2(acc[i][1], ad, bp1);
            ffma2(acc[i][2], ad, bp2);
            ffma2(acc[i][3], ad, bp3);
        }
    }

    // Epilogue: store pred tile + zero label tile. Lanes 0-15 of a warp cover
    // 256 consecutive bytes per row-chunk -> fully coalesced STG.128.
    const ulonglong2 z = make_ulonglong2(0ull, 0ull);
    #pragma unroll
    for (int i = 0; i < 8; i++) {
        int row = m0 + (i < 4 ? tm4a + i : 64 + tm4a + (i - 4));
        size_t off = (size_t)row * I + n0 + tn4a;
        *reinterpret_cast<ulonglong2*>(pred + off) =
            make_ulonglong2(acc[i][0], acc[i][1]);
        *reinterpret_cast<ulonglong2*>(pred + off + 64) =
            make_ulonglong2(acc[i][2], acc[i][3]);
        *reinterpret_cast<ulonglong2*>(label + off)      = z;
        *reinterpret_cast<ulonglong2*>(label + off + 64) = z;
    }
}

// ---------------------------------------------------------------------------
// Kernel 5: scatter-add ratings into label (bounds-guarded)
// ---------------------------------------------------------------------------
__global__ void k_scatter(const void* __restrict__ idx,
                          const float* __restrict__ ratings,
                          float* __restrict__ out, int nnz) {
    int t = blockIdx.x * blockDim.x + threadIdx.x;
    if (t >= nnz) return;
    int u, v;
    read_uv(idx, nnz, t, u, v);
    if (u < 0 || u >= U || v < 0 || v >= I) return;
    float* label = out + (size_t)U * I;
    atomicAdd(&label[(size_t)u * I + v], ratings[t]);
}

// ---------------------------------------------------------------------------
extern "C" void kernel_launch(void* const* d_in, const int* in_sizes, int n_in,
                              void* d_out, int out_size) {
    const float* eu = (const float*)d_in[0];
    const float* ei = (const float*)d_in[1];
    const void*  idx = d_in[2];
    const float* ratings = (const float*)d_in[3];
    float* out = (float*)d_out;
    const int nnz = in_sizes[3];            // ratings count
    const int n_words = in_sizes[2] < 4096 ? in_sizes[2] : 4096;

    // 1. zero masks/flags + detect index dtype (merged)
    k_init<<<(I + 255) / 256, 256>>>((const int*)idx, n_words);
    // 2. set masks/flags from indices
    k_set_masks<<<(nnz + 255) / 256, 256>>>(idx, nnz);
    // 3. masked embedding copies + ratio
    {
        int total = U * (H / 4) + I * (H / 4);
        k_build_scratch<<<(total + 255) / 256, 256>>>(eu, ei, out, nnz,
                                                      (long long)out_size);
    }
    // 4. GEMM (writes pred + zeros label)
    {
        dim3 grid(I / TILE, U / TILE);
        k_gemm<<<grid, 256>>>(out);
    }
    // 5. scatter ratings into label
    k_scatter<<<(nnz + 255) / 256, 256>>>(idx, ratings, out, nnz);
}